// round 13
// baseline (speedup 1.0000x reference)
#include <cuda_runtime.h>

// Problem shape (fixed by setup_inputs): B=4, C=3, H=W=256, kernel [3,1,3,3]
#define Bn   4
#define Cc   3
#define Hh   256
#define Ww   256
#define HW   (Hh * Ww)          // 65536
#define NCH  (Bn * Cc * HW)     // 786432
#define NSC  (Bn * HW)          // 262144

// Tiling: 128 tiles of 32x64 over the [B,H,W] scalar domain -> grid = 128 blocks
#define TY   32
#define TX   64
#define DW   (TX + 4)           // 68  (d tile width, halo 2)
#define TW   (TX + 2)           // 66  (t tile width, halo 1)
#define NBLK 128
#define NTHR 512
#define PPT  ((TY * TX) / NTHR) // 4 interior points per thread
#define NRING 400               // halo-ring entries: 4*68 + 32*4
#define NB_ITERS 101
#define TOLd 1e-6

// -------- device scratch (no allocations allowed) --------
__device__ float  g_r[NCH];          // r ring published once at setup (halo seed)
__device__ float  g_apb[2][NCH];     // Ap ring, double-buffered by iteration parity
__device__ float  g_dscr[NSC];
__device__ double g_pdx[2][NBLK];    // p.Ap   partials (parity-buffered)
__device__ double g_pdy[2][NBLK];    // r.Ap   partials
__device__ double g_pdz[2][NBLK];    // Ap.Ap  partials
__device__ double g_pdw[2][NBLK];    // r.r    partials (TRUE crit of stored r)
__device__ unsigned int g_count = 0;
__device__ unsigned int g_gen   = 0;

// -------- software grid barrier (R5/R8-proven form) --------
__device__ __forceinline__ void gsync() {
    __syncthreads();
    if (threadIdx.x == 0) {
        volatile unsigned int* vgen = &g_gen;
        unsigned int gen = *vgen;
        __threadfence();
        if (atomicAdd(&g_count, 1u) == NBLK - 1u) {
            *((volatile unsigned int*)&g_count) = 0u;
            __threadfence();
            *vgen = gen + 1u;
        } else {
            while (*vgen == gen) { __nanosleep(64); }
        }
        __threadfence();
    }
    __syncthreads();
}

// deterministic 4-way double block reduction; results on thread 0. s: 64 doubles
__device__ __forceinline__ void block_reduce4_d(double& a, double& b, double& c,
                                                double& d, double* s) {
#pragma unroll
    for (int o = 16; o > 0; o >>= 1) {
        a += __shfl_down_sync(0xffffffffu, a, o);
        b += __shfl_down_sync(0xffffffffu, b, o);
        c += __shfl_down_sync(0xffffffffu, c, o);
        d += __shfl_down_sync(0xffffffffu, d, o);
    }
    int w = threadIdx.x >> 5;
    if ((threadIdx.x & 31) == 0) { s[w] = a; s[16 + w] = b; s[32 + w] = c; s[48 + w] = d; }
    __syncthreads();
    if (threadIdx.x < 32) {
        bool in = threadIdx.x < (NTHR / 32);
        a = in ? s[threadIdx.x]      : 0.0;
        b = in ? s[16 + threadIdx.x] : 0.0;
        c = in ? s[32 + threadIdx.x] : 0.0;
        d = in ? s[48 + threadIdx.x] : 0.0;
#pragma unroll
        for (int o = 8; o > 0; o >>= 1) {
            a += __shfl_down_sync(0xffffffffu, a, o);
            b += __shfl_down_sync(0xffffffffu, b, o);
            c += __shfl_down_sync(0xffffffffu, c, o);
            d += __shfl_down_sync(0xffffffffu, d, o);
        }
    }
}

// identical-everywhere reduction of the four double partial arrays
__device__ __forceinline__ void reduce4_arr_d(int par, double* sbc,
                                              double& rx, double& ry,
                                              double& rz, double& rw) {
    __syncthreads();
    if (threadIdx.x < 32) {
        double a = 0.0, b = 0.0, c = 0.0, d = 0.0;
#pragma unroll
        for (int i = 0; i < NBLK / 32; i++) {
            int q = threadIdx.x + i * 32;
            a += __ldcg(&g_pdx[par][q]);
            b += __ldcg(&g_pdy[par][q]);
            c += __ldcg(&g_pdz[par][q]);
            d += __ldcg(&g_pdw[par][q]);
        }
#pragma unroll
        for (int o = 16; o > 0; o >>= 1) {
            a += __shfl_down_sync(0xffffffffu, a, o);
            b += __shfl_down_sync(0xffffffffu, b, o);
            c += __shfl_down_sync(0xffffffffu, c, o);
            d += __shfl_down_sync(0xffffffffu, d, o);
        }
        if (threadIdx.x == 0) { sbc[0] = a; sbc[1] = b; sbc[2] = c; sbc[3] = d; }
    }
    __syncthreads();
    rx = sbc[0]; ry = sbc[1]; rz = sbc[2]; rw = sbc[3];
    __syncthreads();
}

__global__ void __launch_bounds__(NTHR, 1)
cg_kernel(const float* __restrict__ mask, const float* __restrict__ yin,
          const float* __restrict__ zin,  const float* __restrict__ bein,
          const float* __restrict__ rhop, const float* __restrict__ kern,
          float* __restrict__ xout)
{
    __shared__ float  sD[(TY + 4) * DW];      // d tile with halo 2
    __shared__ float  sT[3][(TY + 2) * TW];   // t = P(d) tile with halo 1
    __shared__ double sRedD[64];              // block_reduce staging
    __shared__ double sBc[4];                 // broadcast slots
    __shared__ float  sHm[3][NRING];          // halo mask (loaded once)
    __shared__ float  sHr[3][NRING];          // halo r shadow (recurrence-advanced)
    __shared__ float  sHp[3][NRING];          // halo p shadow

    const int tid = threadIdx.x;
    const int bid = blockIdx.x;

    float kk[27];
#pragma unroll
    for (int i = 0; i < 27; i++) kk[i] = kern[i];
    const float rho = rhop[0];

    // tile decomposition: 4 images x (8 row-tiles x 4 col-tiles) = 128 tiles
    const int bimg = bid >> 5;
    const int tr   = (bid >> 2) & 7;
    const int tc   = bid & 3;
    const int gy0  = tr * TY;
    const int gx0  = tc * TX;
    const int sbase = bimg * HW;          // [B,H,W] base
    const int cbase = bimg * (Cc * HW);   // [B,C,H,W] base

    // register-carried CG state: 4 points x 3 channels per thread
    float xv[PPT][3], rv[PPT][3], pv[PPT][3];
    float mv[PPT];                        // per-point PT(P(d_p)) of current p

    // precomputed halo-slot geometry (threads 0..NRING-1 own one slot each)
    int soff = -1, hidx = -1;
    if (tid < NRING) {
        int ly, lx;
        if (tid < 272) {
            int rr4 = tid / 68;
            ly = (rr4 < 2) ? rr4 : rr4 + 32;   // rows {0,1,34,35}
            lx = tid - rr4 * 68;
        } else {
            int j2 = tid - 272;
            ly = 2 + (j2 >> 2);
            int c4 = j2 & 3;
            lx = (c4 < 2) ? c4 : c4 + 64;      // cols {0,1,66,67}
        }
        soff = ly * DW + lx;
        int gy = gy0 + ly - 2, gx = gx0 + lx - 2;
        if ((unsigned)gy < Hh && (unsigned)gx < Ww)
            hidx = cbase + gy * Ww + gx;
    }

    // t_o[q] = sum_u k_o[1+u] * d[q+u] (corr, zero-padded d), zero outside image
    auto fill_t = [&]() {
        __syncthreads();
#pragma unroll 1
        for (int i = tid; i < (TY + 2) * TW; i += NTHR) {
            int ly = i / TW, lx = i - ly * TW;
            int gy = gy0 + ly - 1, gx = gx0 + lx - 1;
            float t0 = 0.f, t1 = 0.f, t2 = 0.f;
            if ((unsigned)gy < Hh && (unsigned)gx < Ww) {
#pragma unroll
                for (int a = 0; a < 3; a++)
#pragma unroll
                    for (int b2 = 0; b2 < 3; b2++) {
                        float dv = sD[(ly + a) * DW + lx + b2];
                        t0 = fmaf(kk[a * 3 + b2],      dv, t0);
                        t1 = fmaf(kk[9 + a * 3 + b2],  dv, t1);
                        t2 = fmaf(kk[18 + a * 3 + b2], dv, t2);
                    }
            }
            sT[0][i] = t0; sT[1][i] = t1; sT[2][i] = t2;
        }
        __syncthreads();
    };

    // m[p] = sum_o sum_v k_o[1-v] * t_o[p+v] (true conv, t zero outside image)
    auto get_m = [&](int ly, int lx) {
        float m = 0.f;
#pragma unroll
        for (int o = 0; o < 3; o++)
#pragma unroll
            for (int a = 0; a < 3; a++)
#pragma unroll
                for (int b2 = 0; b2 < 3; b2++)
                    m = fmaf(kk[o * 9 + (2 - a) * 3 + (2 - b2)],
                             sT[o][(ly + a) * TW + lx + b2], m);
        return m;
    };

    // ================= setup S1: m_y = PT(P(y)); b = mask*m_y + rho*(z-beta);
    //        x_reg = b; d_x = sum_c mask*b -> g_dscr (full) =================
#pragma unroll 1
    for (int i = tid; i < (TY + 4) * DW; i += NTHR) {
        int ly = i / DW, lx = i - ly * DW;
        int gy = gy0 + ly - 2, gx = gx0 + lx - 2;
        float v = 0.f;
        if ((unsigned)gy < Hh && (unsigned)gx < Ww)
            v = yin[sbase + gy * Ww + gx];
        sD[i] = v;
    }
    fill_t();
#pragma unroll
    for (int j = 0; j < PPT; j++) {
        int i = tid + j * NTHR;
        int ly = i >> 6, lx = i & 63;
        float m = get_m(ly, lx);
        int gy = gy0 + ly, gx = gx0 + lx;
        int idx0 = cbase + gy * Ww + gx;
        float dv = 0.f;
#pragma unroll
        for (int c = 0; c < 3; c++) {
            int idx = idx0 + c * HW;
            float mkv  = __ldg(&mask[idx]);
            float bval = fmaf(mkv, m, rho * (zin[idx] - bein[idx]));
            xv[j][c] = bval;
            dv = fmaf(mkv, bval, dv);
        }
        __stcg(&g_dscr[sbase + gy * Ww + gx], dv);
    }
    gsync();

    // ================= setup S2: r = b - A(b); publish r ring =================
#pragma unroll 1
    for (int i = tid; i < (TY + 4) * DW; i += NTHR) {
        int ly = i / DW, lx = i - ly * DW;
        int gy = gy0 + ly - 2, gx = gx0 + lx - 2;
        float v = 0.f;
        if ((unsigned)gy < Hh && (unsigned)gx < Ww)
            v = __ldcg(&g_dscr[sbase + gy * Ww + gx]);
        sD[i] = v;
    }
    fill_t();
#pragma unroll
    for (int j = 0; j < PPT; j++) {
        int i = tid + j * NTHR;
        int ly = i >> 6, lx = i & 63;
        float m = get_m(ly, lx);
        bool ring = (ly < 2) || (ly >= TY - 2) || (lx < 2) || (lx >= TX - 2);
        int idx0 = cbase + (gy0 + ly) * Ww + (gx0 + lx);
#pragma unroll
        for (int c = 0; c < 3; c++) {
            float bval = xv[j][c];
            float r0 = bval - fmaf(rho, bval, __ldg(&mask[idx0 + c * HW]) * m);
            rv[j][c] = r0;
            pv[j][c] = 0.f;
            if (ring) __stcg(&g_r[idx0 + c * HW], r0);
        }
    }
    gsync();

    // seed halo shadows from the published r ring
    if (tid < NRING) {
#pragma unroll
        for (int c = 0; c < 3; c++) {
            float hm = 0.f, hr = 0.f;
            if (hidx >= 0) {
                hm = __ldg(&mask[hidx + c * HW]);
                hr = __ldcg(&g_r[hidx + c * HW]);
            }
            sHm[c][tid] = hm;
            sHr[c][tid] = hr;
            sHp[c][tid] = 0.f;
        }
    }

    // ================= CG main loop: ONE grid sync per iteration =============
    // alpha uses TRUE crit (measured from stored r each iteration in A3);
    // only beta uses a single-step recurrence re-anchored to the true crit.
    // unroll 1: keep the loop rolled — the body is huge; protects compile time.
    float betaf = 0.f;      // p=0, beta=0 -> fmaf(0,0,r)=r on first iteration
#pragma unroll 1
    for (int k = 1; k <= NB_ITERS; k++) {
        const int par = k & 1;
        float* __restrict__ apb = g_apb[par];

        // ---- A1: interior p = r + beta*p; d = sum_c mask*p (registers) ----
#pragma unroll
        for (int j = 0; j < PPT; j++) {
            int i = tid + j * NTHR;
            int ly = i >> 6, lx = i & 63;
            int idx0 = cbase + (gy0 + ly) * Ww + (gx0 + lx);
            float dv = 0.f;
#pragma unroll
            for (int c = 0; c < 3; c++) {
                float pnew = fmaf(betaf, pv[j][c], rv[j][c]);
                pv[j][c] = pnew;
                dv = fmaf(__ldg(&mask[idx0 + c * HW]), pnew, dv);
            }
            sD[(ly + 2) * DW + (lx + 2)] = dv;
        }

        // ---- A2: halo shadows advance by the SAME recurrence (all smem) ----
        if (tid < NRING) {
            float dv = 0.f;
#pragma unroll
            for (int c = 0; c < 3; c++) {
                float hp = fmaf(betaf, sHp[c][tid], sHr[c][tid]);
                sHp[c][tid] = hp;
                dv = fmaf(sHm[c][tid], hp, dv);
            }
            sD[soff] = dv;
        }

        fill_t();   // __syncthreads inside covers A1+A2

        // ---- A3: m; Ap; publish Ap ring; 4 dot products in DOUBLE
        //      (p.Ap, r.Ap, Ap.Ap, and TRUE r.r from stored r) ----
        {
            double pd = 0.0, rap = 0.0, aa = 0.0, rr = 0.0;
#pragma unroll
            for (int j = 0; j < PPT; j++) {
                int i = tid + j * NTHR;
                int ly = i >> 6, lx = i & 63;
                float m = get_m(ly, lx);
                mv[j] = m;
                bool ring = (ly < 2) || (ly >= TY - 2) || (lx < 2) || (lx >= TX - 2);
                int idx0 = cbase + (gy0 + ly) * Ww + (gx0 + lx);
#pragma unroll
                for (int c = 0; c < 3; c++) {
                    int idx = idx0 + c * HW;
                    float apv = fmaf(rho, pv[j][c], __ldg(&mask[idx]) * m);
                    double apd = (double)apv;
                    double rd  = (double)rv[j][c];
                    pd  = fma((double)pv[j][c], apd, pd);
                    rap = fma(rd, apd, rap);
                    aa  = fma(apd, apd, aa);
                    rr  = fma(rd, rd, rr);
                    if (ring) __stcg(&apb[idx], apv);
                }
            }
            block_reduce4_d(pd, rap, aa, rr, sRedD);
            if (tid == 0) {
                __stcg(&g_pdx[par][bid], pd);
                __stcg(&g_pdy[par][bid], rap);
                __stcg(&g_pdz[par][bid], aa);
                __stcg(&g_pdw[par][bid], rr);
            }
        }
        gsync();   // the ONLY grid sync in the iteration

        // ---- B: crit_true from stored r; freeze test; x,r,halo update ----
        {
            double sx, sy, sz, crit;
            reduce4_arr_d(par, sBc, sx, sy, sz, crit);   // identical everywhere
            if (!(crit >= TOLd)) break;     // reference 'active' gating: frozen
            float  alphaf = (float)(crit / sx);
            double ad     = (double)alphaf;              // track stored fp32 state
            // single-step recurrence, re-anchored to the measured true crit:
            double critn  = fma(ad * ad, sz, fma(-2.0 * ad, sy, crit));
#pragma unroll
            for (int j = 0; j < PPT; j++) {
                int i = tid + j * NTHR;
                int ly = i >> 6, lx = i & 63;
                int idx0 = cbase + (gy0 + ly) * Ww + (gx0 + lx);
#pragma unroll
                for (int c = 0; c < 3; c++) {
                    float apv = fmaf(rho, pv[j][c], __ldg(&mask[idx0 + c * HW]) * mv[j]);
                    xv[j][c] = fmaf(alphaf, pv[j][c], xv[j][c]);
                    rv[j][c] = fmaf(-alphaf, apv, rv[j][c]);
                }
            }
            if (tid < NRING && hidx >= 0) {
#pragma unroll
                for (int c = 0; c < 3; c++) {
                    float hap = __ldcg(&apb[hidx + c * HW]);
                    sHr[c][tid] = fmaf(-alphaf, hap, sHr[c][tid]);
                }
            }
            betaf = (float)(critn / crit);
        }
        // no sync needed: next A reads only block-local state; parity buffers
        // make the next publish race-free vs this B's reads.
    }

    // ================= final: write x from registers (own points) ==========
#pragma unroll
    for (int j = 0; j < PPT; j++) {
        int i = tid + j * NTHR;
        int ly = i >> 6, lx = i & 63;
        int idx0 = cbase + (gy0 + ly) * Ww + (gx0 + lx);
#pragma unroll
        for (int c = 0; c < 3; c++)
            xout[idx0 + c * HW] = xv[j][c];
    }
}

extern "C" void kernel_launch(void* const* d_in, const int* in_sizes, int n_in,
                              void* d_out, int out_size) {
    (void)in_sizes; (void)n_in; (void)out_size;
    cg_kernel<<<NBLK, NTHR>>>(
        (const float*)d_in[0],   // mask  [4,3,256,256]
        (const float*)d_in[1],   // y     [4,256,256]
        (const float*)d_in[2],   // z     [4,3,256,256]
        (const float*)d_in[3],   // beta  [4,3,256,256]
        (const float*)d_in[4],   // rho   scalar
        (const float*)d_in[5],   // kernel[3,1,3,3]
        (float*)d_out);          // x     [4,3,256,256]
}

// round 14
// speedup vs baseline: 3.8832x; 3.8832x over previous
#include <cuda_runtime.h>

// Problem shape (fixed by setup_inputs): B=4, C=3, H=W=256, kernel [3,1,3,3]
#define Bn   4
#define Cc   3
#define Hh   256
#define Ww   256
#define HW   (Hh * Ww)          // 65536
#define NCH  (Bn * Cc * HW)     // 786432
#define NSC  (Bn * HW)          // 262144

// Tiling: 128 tiles of 32x64 over the [B,H,W] scalar domain -> grid = 128 blocks
#define TY   32
#define TX   64
#define DW   (TX + 4)           // 68  (d tile width, halo 2)
#define TW   (TX + 2)           // 66  (t tile width, halo 1)
#define NBLK 128
#define NTHR 512
#define PPT  ((TY * TX) / NTHR) // 4 interior points per thread
#define NRING 400               // halo-ring entries: 4*68 + 32*4
#define NB_ITERS 101
#define TOLf 1e-6f

// -------- device scratch (no allocations allowed) --------
__device__ float  g_r[NCH];          // r ring published once at setup (halo seed)
__device__ float  g_apb[2][NCH];     // Ap ring, double-buffered by iteration parity
__device__ float  g_dscr[NSC];
__device__ float4 g_pd4[2][NBLK];    // (p.Ap, r.Ap, Ap.Ap, r.r) partials, parity-buffered
__device__ unsigned int g_count = 0;
__device__ unsigned int g_gen   = 0;

// -------- software grid barrier (R5/R8-proven form) --------
__device__ __forceinline__ void gsync() {
    __syncthreads();
    if (threadIdx.x == 0) {
        volatile unsigned int* vgen = &g_gen;
        unsigned int gen = *vgen;
        __threadfence();
        if (atomicAdd(&g_count, 1u) == NBLK - 1u) {
            *((volatile unsigned int*)&g_count) = 0u;
            __threadfence();
            *vgen = gen + 1u;
        } else {
            while (*vgen == gen) { __nanosleep(64); }
        }
        __threadfence();
    }
    __syncthreads();
}

// deterministic 4-way fp32 block tree reduction; results on thread 0. s: 64 floats
__device__ __forceinline__ void block_reduce4(float& a, float& b, float& c,
                                              float& d, float* s) {
#pragma unroll
    for (int o = 16; o > 0; o >>= 1) {
        a += __shfl_down_sync(0xffffffffu, a, o);
        b += __shfl_down_sync(0xffffffffu, b, o);
        c += __shfl_down_sync(0xffffffffu, c, o);
        d += __shfl_down_sync(0xffffffffu, d, o);
    }
    int w = threadIdx.x >> 5;
    if ((threadIdx.x & 31) == 0) { s[w] = a; s[16 + w] = b; s[32 + w] = c; s[48 + w] = d; }
    __syncthreads();
    if (threadIdx.x < 32) {
        bool in = threadIdx.x < (NTHR / 32);
        a = in ? s[threadIdx.x]      : 0.f;
        b = in ? s[16 + threadIdx.x] : 0.f;
        c = in ? s[32 + threadIdx.x] : 0.f;
        d = in ? s[48 + threadIdx.x] : 0.f;
#pragma unroll
        for (int o = 8; o > 0; o >>= 1) {
            a += __shfl_down_sync(0xffffffffu, a, o);
            b += __shfl_down_sync(0xffffffffu, b, o);
            c += __shfl_down_sync(0xffffffffu, c, o);
            d += __shfl_down_sync(0xffffffffu, d, o);
        }
    }
}

// identical-everywhere reduction of the 128 float4 partials (fixed order)
__device__ __forceinline__ void reduce4_arr(int par, float* sbc,
                                            float& rx, float& ry,
                                            float& rz, float& rw) {
    __syncthreads();
    if (threadIdx.x < 32) {
        float a = 0.f, b = 0.f, c = 0.f, d = 0.f;
#pragma unroll
        for (int i = 0; i < NBLK / 32; i++) {
            float4 v = __ldcg(&g_pd4[par][threadIdx.x + i * 32]);
            a += v.x; b += v.y; c += v.z; d += v.w;
        }
#pragma unroll
        for (int o = 16; o > 0; o >>= 1) {
            a += __shfl_down_sync(0xffffffffu, a, o);
            b += __shfl_down_sync(0xffffffffu, b, o);
            c += __shfl_down_sync(0xffffffffu, c, o);
            d += __shfl_down_sync(0xffffffffu, d, o);
        }
        if (threadIdx.x == 0) { sbc[0] = a; sbc[1] = b; sbc[2] = c; sbc[3] = d; }
    }
    __syncthreads();
    rx = sbc[0]; ry = sbc[1]; rz = sbc[2]; rw = sbc[3];
    __syncthreads();
}

__global__ void __launch_bounds__(NTHR, 1)
cg_kernel(const float* __restrict__ mask, const float* __restrict__ yin,
          const float* __restrict__ zin,  const float* __restrict__ bein,
          const float* __restrict__ rhop, const float* __restrict__ kern,
          float* __restrict__ xout)
{
    __shared__ float sD[(TY + 4) * DW];       // d tile with halo 2
    __shared__ float sT[3][(TY + 2) * TW];    // t = P(d) tile with halo 1
    __shared__ float sRed[64];                // block_reduce staging
    __shared__ float sBc[4];                  // broadcast slots
    __shared__ float sHm[3][NRING];           // halo mask (loaded once)
    __shared__ float sHr[3][NRING];           // halo r shadow (recurrence-advanced)
    __shared__ float sHp[3][NRING];           // halo p shadow

    const int tid = threadIdx.x;
    const int bid = blockIdx.x;

    float kk[27];
#pragma unroll
    for (int i = 0; i < 27; i++) kk[i] = kern[i];
    const float rho = rhop[0];

    // tile decomposition: 4 images x (8 row-tiles x 4 col-tiles) = 128 tiles
    const int bimg = bid >> 5;
    const int tr   = (bid >> 2) & 7;
    const int tc   = bid & 3;
    const int gy0  = tr * TY;
    const int gx0  = tc * TX;
    const int sbase = bimg * HW;          // [B,H,W] base
    const int cbase = bimg * (Cc * HW);   // [B,C,H,W] base

    // register-carried CG state: 4 points x 3 channels per thread
    float xv[PPT][3], rv[PPT][3], pv[PPT][3];
    float mv[PPT];                        // per-point PT(P(d_p)) of current p

    // precomputed halo-slot geometry (threads 0..NRING-1 own one slot each)
    int soff = -1, hidx = -1;
    if (tid < NRING) {
        int ly, lx;
        if (tid < 272) {
            int rr4 = tid / 68;
            ly = (rr4 < 2) ? rr4 : rr4 + 32;   // rows {0,1,34,35}
            lx = tid - rr4 * 68;
        } else {
            int j2 = tid - 272;
            ly = 2 + (j2 >> 2);
            int c4 = j2 & 3;
            lx = (c4 < 2) ? c4 : c4 + 64;      // cols {0,1,66,67}
        }
        soff = ly * DW + lx;
        int gy = gy0 + ly - 2, gx = gx0 + lx - 2;
        if ((unsigned)gy < Hh && (unsigned)gx < Ww)
            hidx = cbase + gy * Ww + gx;
    }

    // t_o[q] = sum_u k_o[1+u] * d[q+u] (corr, zero-padded d), zero outside image
    auto fill_t = [&]() {
        __syncthreads();
#pragma unroll 1
        for (int i = tid; i < (TY + 2) * TW; i += NTHR) {
            int ly = i / TW, lx = i - ly * TW;
            int gy = gy0 + ly - 1, gx = gx0 + lx - 1;
            float t0 = 0.f, t1 = 0.f, t2 = 0.f;
            if ((unsigned)gy < Hh && (unsigned)gx < Ww) {
#pragma unroll
                for (int a = 0; a < 3; a++)
#pragma unroll
                    for (int b2 = 0; b2 < 3; b2++) {
                        float dv = sD[(ly + a) * DW + lx + b2];
                        t0 = fmaf(kk[a * 3 + b2],      dv, t0);
                        t1 = fmaf(kk[9 + a * 3 + b2],  dv, t1);
                        t2 = fmaf(kk[18 + a * 3 + b2], dv, t2);
                    }
            }
            sT[0][i] = t0; sT[1][i] = t1; sT[2][i] = t2;
        }
        __syncthreads();
    };

    // m[p] = sum_o sum_v k_o[1-v] * t_o[p+v] (true conv, t zero outside image)
    auto get_m = [&](int ly, int lx) {
        float m = 0.f;
#pragma unroll
        for (int o = 0; o < 3; o++)
#pragma unroll
            for (int a = 0; a < 3; a++)
#pragma unroll
                for (int b2 = 0; b2 < 3; b2++)
                    m = fmaf(kk[o * 9 + (2 - a) * 3 + (2 - b2)],
                             sT[o][(ly + a) * TW + lx + b2], m);
        return m;
    };

    // ================= setup S1: m_y = PT(P(y)); b = mask*m_y + rho*(z-beta);
    //        x_reg = b; d_x = sum_c mask*b -> g_dscr (full) =================
#pragma unroll 1
    for (int i = tid; i < (TY + 4) * DW; i += NTHR) {
        int ly = i / DW, lx = i - ly * DW;
        int gy = gy0 + ly - 2, gx = gx0 + lx - 2;
        float v = 0.f;
        if ((unsigned)gy < Hh && (unsigned)gx < Ww)
            v = yin[sbase + gy * Ww + gx];
        sD[i] = v;
    }
    fill_t();
#pragma unroll
    for (int j = 0; j < PPT; j++) {
        int i = tid + j * NTHR;
        int ly = i >> 6, lx = i & 63;
        float m = get_m(ly, lx);
        int gy = gy0 + ly, gx = gx0 + lx;
        int idx0 = cbase + gy * Ww + gx;
        float dv = 0.f;
#pragma unroll
        for (int c = 0; c < 3; c++) {
            int idx = idx0 + c * HW;
            float mkv  = __ldg(&mask[idx]);
            float bval = fmaf(mkv, m, rho * (zin[idx] - bein[idx]));
            xv[j][c] = bval;
            dv = fmaf(mkv, bval, dv);
        }
        __stcg(&g_dscr[sbase + gy * Ww + gx], dv);
    }
    gsync();

    // ================= setup S2: r = b - A(b); publish r ring =================
#pragma unroll 1
    for (int i = tid; i < (TY + 4) * DW; i += NTHR) {
        int ly = i / DW, lx = i - ly * DW;
        int gy = gy0 + ly - 2, gx = gx0 + lx - 2;
        float v = 0.f;
        if ((unsigned)gy < Hh && (unsigned)gx < Ww)
            v = __ldcg(&g_dscr[sbase + gy * Ww + gx]);
        sD[i] = v;
    }
    fill_t();
#pragma unroll
    for (int j = 0; j < PPT; j++) {
        int i = tid + j * NTHR;
        int ly = i >> 6, lx = i & 63;
        float m = get_m(ly, lx);
        bool ring = (ly < 2) || (ly >= TY - 2) || (lx < 2) || (lx >= TX - 2);
        int idx0 = cbase + (gy0 + ly) * Ww + (gx0 + lx);
#pragma unroll
        for (int c = 0; c < 3; c++) {
            float bval = xv[j][c];
            float r0 = bval - fmaf(rho, bval, __ldg(&mask[idx0 + c * HW]) * m);
            rv[j][c] = r0;
            pv[j][c] = 0.f;
            if (ring) __stcg(&g_r[idx0 + c * HW], r0);
        }
    }
    gsync();

    // seed halo shadows from the published r ring
    if (tid < NRING) {
#pragma unroll
        for (int c = 0; c < 3; c++) {
            float hm = 0.f, hr = 0.f;
            if (hidx >= 0) {
                hm = __ldg(&mask[hidx + c * HW]);
                hr = __ldcg(&g_r[hidx + c * HW]);
            }
            sHm[c][tid] = hm;
            sHr[c][tid] = hr;
            sHp[c][tid] = 0.f;
        }
    }

    // ================= CG main loop: ONE grid sync per iteration =============
    // alpha uses the TRUE crit (r.r measured from stored r each iteration, in
    // A3, riding the same barrier). Only beta uses a SINGLE-STEP recurrence
    // re-anchored to that true crit -> no compounding drift. All fp32: the
    // fp64 pipe on sm_103a is ~10x too slow for per-element use (R13 lesson).
    float betaf = 0.f;      // p=0, beta=0 -> fmaf(0,0,r)=r on first iteration
#pragma unroll 1
    for (int k = 1; k <= NB_ITERS; k++) {
        const int par = k & 1;
        float* __restrict__ apb = g_apb[par];

        // ---- A1: interior p = r + beta*p; d = sum_c mask*p (registers) ----
#pragma unroll
        for (int j = 0; j < PPT; j++) {
            int i = tid + j * NTHR;
            int ly = i >> 6, lx = i & 63;
            int idx0 = cbase + (gy0 + ly) * Ww + (gx0 + lx);
            float dv = 0.f;
#pragma unroll
            for (int c = 0; c < 3; c++) {
                float pnew = fmaf(betaf, pv[j][c], rv[j][c]);
                pv[j][c] = pnew;
                dv = fmaf(__ldg(&mask[idx0 + c * HW]), pnew, dv);
            }
            sD[(ly + 2) * DW + (lx + 2)] = dv;
        }

        // ---- A2: halo shadows advance by the SAME recurrence (all smem) ----
        if (tid < NRING) {
            float dv = 0.f;
#pragma unroll
            for (int c = 0; c < 3; c++) {
                float hp = fmaf(betaf, sHp[c][tid], sHr[c][tid]);
                sHp[c][tid] = hp;
                dv = fmaf(sHm[c][tid], hp, dv);
            }
            sD[soff] = dv;
        }

        fill_t();   // __syncthreads inside covers A1+A2

        // ---- A3: m; Ap; publish Ap ring; 4 fp32 dot products
        //      (p.Ap, r.Ap, Ap.Ap, TRUE r.r of stored r) ----
        {
            float pd = 0.f, rap = 0.f, aa = 0.f, rr = 0.f;
#pragma unroll
            for (int j = 0; j < PPT; j++) {
                int i = tid + j * NTHR;
                int ly = i >> 6, lx = i & 63;
                float m = get_m(ly, lx);
                mv[j] = m;
                bool ring = (ly < 2) || (ly >= TY - 2) || (lx < 2) || (lx >= TX - 2);
                int idx0 = cbase + (gy0 + ly) * Ww + (gx0 + lx);
#pragma unroll
                for (int c = 0; c < 3; c++) {
                    int idx = idx0 + c * HW;
                    float apv = fmaf(rho, pv[j][c], __ldg(&mask[idx]) * m);
                    pd  = fmaf(pv[j][c], apv, pd);
                    rap = fmaf(rv[j][c], apv, rap);
                    aa  = fmaf(apv, apv, aa);
                    rr  = fmaf(rv[j][c], rv[j][c], rr);
                    if (ring) __stcg(&apb[idx], apv);
                }
            }
            block_reduce4(pd, rap, aa, rr, sRed);
            if (tid == 0)
                __stcg(&g_pd4[par][bid], make_float4(pd, rap, aa, rr));
        }
        gsync();   // the ONLY grid sync in the iteration

        // ---- B: crit_true from stored r; freeze test; x,r,halo update ----
        {
            float sx, sy, sz, crit;
            reduce4_arr(par, sBc, sx, sy, sz, crit);     // identical everywhere
            if (!(crit >= TOLf)) break;     // reference 'active' gating: frozen
            float alphaf = crit / sx;
            // single-step recurrence, re-anchored to the measured true crit:
            float critn = fmaf(alphaf * alphaf, sz, fmaf(-2.f * alphaf, sy, crit));
            if (critn < 0.f) critn = 0.f;   // fp32 noise guard near convergence
#pragma unroll
            for (int j = 0; j < PPT; j++) {
                int i = tid + j * NTHR;
                int ly = i >> 6, lx = i & 63;
                int idx0 = cbase + (gy0 + ly) * Ww + (gx0 + lx);
#pragma unroll
                for (int c = 0; c < 3; c++) {
                    float apv = fmaf(rho, pv[j][c], __ldg(&mask[idx0 + c * HW]) * mv[j]);
                    xv[j][c] = fmaf(alphaf, pv[j][c], xv[j][c]);
                    rv[j][c] = fmaf(-alphaf, apv, rv[j][c]);
                }
            }
            if (tid < NRING && hidx >= 0) {
#pragma unroll
                for (int c = 0; c < 3; c++) {
                    float hap = __ldcg(&apb[hidx + c * HW]);
                    sHr[c][tid] = fmaf(-alphaf, hap, sHr[c][tid]);
                }
            }
            betaf = critn / crit;
        }
        // no sync needed: next A reads only block-local state; parity buffers
        // make the next publish race-free vs this B's reads.
    }

    // ================= final: write x from registers (own points) ==========
#pragma unroll
    for (int j = 0; j < PPT; j++) {
        int i = tid + j * NTHR;
        int ly = i >> 6, lx = i & 63;
        int idx0 = cbase + (gy0 + ly) * Ww + (gx0 + lx);
#pragma unroll
        for (int c = 0; c < 3; c++)
            xout[idx0 + c * HW] = xv[j][c];
    }
}

extern "C" void kernel_launch(void* const* d_in, const int* in_sizes, int n_in,
                              void* d_out, int out_size) {
    (void)in_sizes; (void)n_in; (void)out_size;
    cg_kernel<<<NBLK, NTHR>>>(
        (const float*)d_in[0],   // mask  [4,3,256,256]
        (const float*)d_in[1],   // y     [4,256,256]
        (const float*)d_in[2],   // z     [4,3,256,256]
        (const float*)d_in[3],   // beta  [4,3,256,256]
        (const float*)d_in[4],   // rho   scalar
        (const float*)d_in[5],   // kernel[3,1,3,3]
        (float*)d_out);          // x     [4,3,256,256]
}

// round 15
// speedup vs baseline: 4.0036x; 1.0310x over previous
#include <cuda_runtime.h>

// Problem shape (fixed by setup_inputs): B=4, C=3, H=W=256, kernel [3,1,3,3]
#define Bn   4
#define Cc   3
#define Hh   256
#define Ww   256
#define HW   (Hh * Ww)          // 65536
#define NCH  (Bn * Cc * HW)     // 786432
#define NSC  (Bn * HW)          // 262144

// Tiling: 128 tiles of 32x64 over the [B,H,W] scalar domain -> grid = 128 blocks
#define TY   32
#define TX   64
#define SDW  72                 // padded d-tile width: halo cols at 2,3 / 68,69; interior at 4+lx (16B-aligned)
#define STW  68                 // padded t-tile width (34 rows x 66 used cols)
#define NBLK 128
#define NTHR 512
#define PPT  4                  // 4 CONSECUTIVE points per thread (one row segment)
#define NRING 400               // halo-ring entries: 4*68 + 32*4
#define NB_ITERS 101
#define TOLf 1e-6f

// -------- device scratch (no allocations allowed) --------
__device__ float  g_r[NCH];          // r ring published once at setup (halo seed)
__device__ float  g_apb[2][NCH];     // Ap ring, double-buffered by iteration parity
__device__ float  g_dscr[NSC];
__device__ float4 g_pd4[2][NBLK];    // (p.Ap, r.Ap, Ap.Ap, r.r) partials, parity-buffered
__device__ unsigned int g_count = 0;
__device__ unsigned int g_gen   = 0;

// -------- software grid barrier (R5/R8-proven form) --------
__device__ __forceinline__ void gsync() {
    __syncthreads();
    if (threadIdx.x == 0) {
        volatile unsigned int* vgen = &g_gen;
        unsigned int gen = *vgen;
        __threadfence();
        if (atomicAdd(&g_count, 1u) == NBLK - 1u) {
            *((volatile unsigned int*)&g_count) = 0u;
            __threadfence();
            *vgen = gen + 1u;
        } else {
            while (*vgen == gen) { __nanosleep(64); }
        }
        __threadfence();
    }
    __syncthreads();
}

// deterministic 4-way fp32 block tree reduction; results on thread 0. s: 64 floats
__device__ __forceinline__ void block_reduce4(float& a, float& b, float& c,
                                              float& d, float* s) {
#pragma unroll
    for (int o = 16; o > 0; o >>= 1) {
        a += __shfl_down_sync(0xffffffffu, a, o);
        b += __shfl_down_sync(0xffffffffu, b, o);
        c += __shfl_down_sync(0xffffffffu, c, o);
        d += __shfl_down_sync(0xffffffffu, d, o);
    }
    int w = threadIdx.x >> 5;
    if ((threadIdx.x & 31) == 0) { s[w] = a; s[16 + w] = b; s[32 + w] = c; s[48 + w] = d; }
    __syncthreads();
    if (threadIdx.x < 32) {
        bool in = threadIdx.x < (NTHR / 32);
        a = in ? s[threadIdx.x]      : 0.f;
        b = in ? s[16 + threadIdx.x] : 0.f;
        c = in ? s[32 + threadIdx.x] : 0.f;
        d = in ? s[48 + threadIdx.x] : 0.f;
#pragma unroll
        for (int o = 8; o > 0; o >>= 1) {
            a += __shfl_down_sync(0xffffffffu, a, o);
            b += __shfl_down_sync(0xffffffffu, b, o);
            c += __shfl_down_sync(0xffffffffu, c, o);
            d += __shfl_down_sync(0xffffffffu, d, o);
        }
    }
}

// identical-everywhere reduction of the 128 float4 partials (fixed order)
__device__ __forceinline__ void reduce4_arr(int par, float* sbc,
                                            float& rx, float& ry,
                                            float& rz, float& rw) {
    __syncthreads();
    if (threadIdx.x < 32) {
        float a = 0.f, b = 0.f, c = 0.f, d = 0.f;
#pragma unroll
        for (int i = 0; i < NBLK / 32; i++) {
            float4 v = __ldcg(&g_pd4[par][threadIdx.x + i * 32]);
            a += v.x; b += v.y; c += v.z; d += v.w;
        }
#pragma unroll
        for (int o = 16; o > 0; o >>= 1) {
            a += __shfl_down_sync(0xffffffffu, a, o);
            b += __shfl_down_sync(0xffffffffu, b, o);
            c += __shfl_down_sync(0xffffffffu, c, o);
            d += __shfl_down_sync(0xffffffffu, d, o);
        }
        if (threadIdx.x == 0) { sbc[0] = a; sbc[1] = b; sbc[2] = c; sbc[3] = d; }
    }
    __syncthreads();
    rx = sbc[0]; ry = sbc[1]; rz = sbc[2]; rw = sbc[3];
    __syncthreads();
}

__global__ void __launch_bounds__(NTHR, 1)
cg_kernel(const float* __restrict__ mask, const float* __restrict__ yin,
          const float* __restrict__ zin,  const float* __restrict__ bein,
          const float* __restrict__ rhop, const float* __restrict__ kern,
          float* __restrict__ xout)
{
    __shared__ __align__(16) float sD[36 * SDW];        // d tile with halo 2 (padded)
    __shared__ __align__(16) float sT[3][34 * STW];     // t = P(d) tile with halo 1 (padded)
    __shared__ float sRed[64];                // block_reduce staging
    __shared__ float sBc[4];                  // broadcast slots
    __shared__ float sHm[3][NRING];           // halo mask (loaded once)
    __shared__ float sHr[3][NRING];           // halo r shadow (recurrence-advanced)
    __shared__ float sHp[3][NRING];           // halo p shadow

    const int tid = threadIdx.x;
    const int bid = blockIdx.x;

    float kk[27];
#pragma unroll
    for (int i = 0; i < 27; i++) kk[i] = kern[i];
    const float rho = rhop[0];

    // tile decomposition: 4 images x (8 row-tiles x 4 col-tiles) = 128 tiles
    const int bimg = bid >> 5;
    const int tr   = (bid >> 2) & 7;
    const int tc   = bid & 3;
    const int gy0  = tr * TY;
    const int gx0  = tc * TX;
    const int sbase = bimg * HW;          // [B,H,W] base
    const int cbase = bimg * (Cc * HW);   // [B,C,H,W] base

    // contiguous ownership: thread owns points (ly, lx0..lx0+3)
    const int ly  = tid >> 4;             // 0..31
    const int lx0 = (tid & 15) * 4;       // 0,4,...,60
    const bool rowring = (ly < 2) || (ly >= TY - 2);
    const int idxP = cbase + (gy0 + ly) * Ww + gx0 + lx0;   // [B,C,H,W] point base (c=0)

    // register-carried CG state: [j = x-offset][c = channel]
    float xv[PPT][3], rv[PPT][3], pv[PPT][3];
    float mv[PPT];                        // per-point PT(P(d_p)) of current p

    // precomputed halo-slot geometry (threads 0..NRING-1 own one slot each)
    int soff = -1, hidx = -1;
    if (tid < NRING) {
        int ly2, lxx;
        if (tid < 272) {
            int rr4 = tid / 68;
            ly2 = (rr4 < 2) ? rr4 : rr4 + 32;  // halo rows {0,1,34,35} of 36
            lxx = tid - rr4 * 68;
        } else {
            int j2 = tid - 272;
            ly2 = 2 + (j2 >> 2);
            int c4 = j2 & 3;
            lxx = (c4 < 2) ? c4 : c4 + 64;     // halo cols {0,1,66,67} of 68
        }
        soff = ly2 * SDW + lxx + 2;            // padded layout
        int gy = gy0 + ly2 - 2, gx = gx0 + lxx - 2;
        if ((unsigned)gy < Hh && (unsigned)gx < Ww)
            hidx = cbase + gy * Ww + gx;
    }

    // t_o(ty,tx) = sum_u k_o[1+u]*d[..] (corr, zero-padded d), zero outside image
    auto fill_t = [&]() {
        __syncthreads();
#pragma unroll 1
        for (int i = tid; i < 34 * 66; i += NTHR) {
            int ty = i / 66, tx = i - ty * 66;
            int gy = gy0 + ty - 1, gx = gx0 + tx - 1;
            float t0 = 0.f, t1 = 0.f, t2 = 0.f;
            if ((unsigned)gy < Hh && (unsigned)gx < Ww) {
#pragma unroll
                for (int a = 0; a < 3; a++)
#pragma unroll
                    for (int b2 = 0; b2 < 3; b2++) {
                        float dv = sD[(ty + a) * SDW + tx + b2 + 2];
                        t0 = fmaf(kk[a * 3 + b2],      dv, t0);
                        t1 = fmaf(kk[9 + a * 3 + b2],  dv, t1);
                        t2 = fmaf(kk[18 + a * 3 + b2], dv, t2);
                    }
            }
            int si = ty * STW + tx;
            sT[0][si] = t0; sT[1][si] = t1; sT[2][si] = t2;
        }
        __syncthreads();
    };

    // m for 4 consecutive points; per-point accumulation order IDENTICAL to the
    // scalar get_m (o -> a -> b2), so results are bitwise-equal to R14.
    auto get_m4 = [&](float* out) {
        float a0 = 0.f, a1 = 0.f, a2 = 0.f, a3 = 0.f;
#pragma unroll
        for (int o = 0; o < 3; o++)
#pragma unroll
            for (int a = 0; a < 3; a++) {
                const float4* bp = reinterpret_cast<const float4*>(
                    &sT[o][(ly + a) * STW + lx0]);
                float4 lo = bp[0], hi = bp[1];
                float w0 = kk[o * 9 + (2 - a) * 3 + 2];   // b2=0
                float w1 = kk[o * 9 + (2 - a) * 3 + 1];   // b2=1
                float w2 = kk[o * 9 + (2 - a) * 3 + 0];   // b2=2
                a0 = fmaf(w0, lo.x, a0); a0 = fmaf(w1, lo.y, a0); a0 = fmaf(w2, lo.z, a0);
                a1 = fmaf(w0, lo.y, a1); a1 = fmaf(w1, lo.z, a1); a1 = fmaf(w2, lo.w, a1);
                a2 = fmaf(w0, lo.z, a2); a2 = fmaf(w1, lo.w, a2); a2 = fmaf(w2, hi.x, a2);
                a3 = fmaf(w0, lo.w, a3); a3 = fmaf(w1, hi.x, a3); a3 = fmaf(w2, hi.y, a3);
            }
        out[0] = a0; out[1] = a1; out[2] = a2; out[3] = a3;
    };

    // ================= setup S1: m_y = PT(P(y)); b = mask*m_y + rho*(z-beta);
    //        x_reg = b; d_x = sum_c mask*b -> g_dscr (full) =================
#pragma unroll 1
    for (int i = tid; i < 36 * 68; i += NTHR) {
        int ly2 = i / 68, lxx = i - ly2 * 68;
        int gy = gy0 + ly2 - 2, gx = gx0 + lxx - 2;
        float v = 0.f;
        if ((unsigned)gy < Hh && (unsigned)gx < Ww)
            v = yin[sbase + gy * Ww + gx];
        sD[ly2 * SDW + lxx + 2] = v;
    }
    fill_t();
    {
        float m4a[PPT]; get_m4(m4a);
        float dv[PPT] = {0.f, 0.f, 0.f, 0.f};
#pragma unroll
        for (int c = 0; c < 3; c++) {
            float4 mk4 = __ldg((const float4*)&mask[idxP + c * HW]);
            float4 z4  = __ldg((const float4*)&zin[idxP + c * HW]);
            float4 be4 = __ldg((const float4*)&bein[idxP + c * HW]);
            float mkj[4] = {mk4.x, mk4.y, mk4.z, mk4.w};
            float zj[4]  = {z4.x, z4.y, z4.z, z4.w};
            float bj[4]  = {be4.x, be4.y, be4.z, be4.w};
#pragma unroll
            for (int j = 0; j < PPT; j++) {
                float bval = fmaf(mkj[j], m4a[j], rho * (zj[j] - bj[j]));
                xv[j][c] = bval;
                dv[j] = fmaf(mkj[j], bval, dv[j]);
            }
        }
        *(float4*)&g_dscr[sbase + (gy0 + ly) * Ww + gx0 + lx0] =
            make_float4(dv[0], dv[1], dv[2], dv[3]);
    }
    gsync();

    // ================= setup S2: r = b - A(b); publish r ring =================
#pragma unroll 1
    for (int i = tid; i < 36 * 68; i += NTHR) {
        int ly2 = i / 68, lxx = i - ly2 * 68;
        int gy = gy0 + ly2 - 2, gx = gx0 + lxx - 2;
        float v = 0.f;
        if ((unsigned)gy < Hh && (unsigned)gx < Ww)
            v = __ldcg(&g_dscr[sbase + gy * Ww + gx]);
        sD[ly2 * SDW + lxx + 2] = v;
    }
    fill_t();
    {
        float m4a[PPT]; get_m4(m4a);
#pragma unroll
        for (int c = 0; c < 3; c++) {
            float4 mk4 = __ldg((const float4*)&mask[idxP + c * HW]);
            float mkj[4] = {mk4.x, mk4.y, mk4.z, mk4.w};
            float r4[4];
#pragma unroll
            for (int j = 0; j < PPT; j++) {
                float bval = xv[j][c];
                float r0 = bval - fmaf(rho, bval, mkj[j] * m4a[j]);
                rv[j][c] = r0;
                r4[j] = r0;
            }
            if (rowring) {
                *(float4*)&g_r[idxP + c * HW] = make_float4(r4[0], r4[1], r4[2], r4[3]);
            } else if (lx0 == 0) {
                g_r[idxP + c * HW]     = r4[0];
                g_r[idxP + c * HW + 1] = r4[1];
            } else if (lx0 == TX - 4) {
                g_r[idxP + c * HW + 2] = r4[2];
                g_r[idxP + c * HW + 3] = r4[3];
            }
        }
    }
    gsync();

    // seed halo shadows from the published r ring
    if (tid < NRING) {
#pragma unroll
        for (int c = 0; c < 3; c++) {
            float hm = 0.f, hr = 0.f;
            if (hidx >= 0) {
                hm = __ldg(&mask[hidx + c * HW]);
                hr = __ldcg(&g_r[hidx + c * HW]);
            }
            sHm[c][tid] = hm;
            sHr[c][tid] = hr;
            sHp[c][tid] = 0.f;
        }
    }

    // prologue: p = r (classic CG start); fill sD for the first fill_t
    {
        float dv[PPT] = {0.f, 0.f, 0.f, 0.f};
#pragma unroll
        for (int c = 0; c < 3; c++) {
            float4 mk4 = __ldg((const float4*)&mask[idxP + c * HW]);
            float mkj[4] = {mk4.x, mk4.y, mk4.z, mk4.w};
#pragma unroll
            for (int j = 0; j < PPT; j++) {
                pv[j][c] = rv[j][c];
                dv[j] = fmaf(mkj[j], pv[j][c], dv[j]);
            }
        }
        *(float4*)&sD[(ly + 2) * SDW + lx0 + 4] = make_float4(dv[0], dv[1], dv[2], dv[3]);
    }
    if (tid < NRING) {
        float dvh = 0.f;
        if (hidx >= 0) {
#pragma unroll
            for (int c = 0; c < 3; c++) {
                float hp = sHr[c][tid];
                sHp[c][tid] = hp;
                dvh = fmaf(sHm[c][tid], hp, dvh);
            }
        }
        sD[soff] = dvh;   // out-of-image slots stay 0 forever
    }

    // ================= CG main loop: ONE grid sync per iteration =============
    // alpha uses the TRUE crit (r.r from stored r, measured in A3). beta uses a
    // SINGLE-STEP recurrence re-anchored to that crit (no compounding drift).
    // All fp32 (sm_103a fp64 pipe is ~10x too slow — R13 lesson).
    // Loop body: fill_t -> A3 -> gsync -> fused B (scalars; x,r,p update; sD refill).
#pragma unroll 1
    for (int k = 1; k <= NB_ITERS; k++) {
        const int par = k & 1;
        float* __restrict__ apb = g_apb[par];

        fill_t();

        // ---- A3: m; Ap; publish Ap ring; 4 fp32 dot products ----
        {
            float m4a[PPT]; get_m4(m4a);
            mv[0] = m4a[0]; mv[1] = m4a[1]; mv[2] = m4a[2]; mv[3] = m4a[3];
            float pd = 0.f, rap = 0.f, aa = 0.f, rr = 0.f;
#pragma unroll
            for (int c = 0; c < 3; c++) {
                float4 mk4 = __ldg((const float4*)&mask[idxP + c * HW]);
                float mkj[4] = {mk4.x, mk4.y, mk4.z, mk4.w};
                float ap[4];
#pragma unroll
                for (int j = 0; j < PPT; j++) {
                    ap[j] = fmaf(rho, pv[j][c], mkj[j] * m4a[j]);
                    pd  = fmaf(pv[j][c], ap[j], pd);
                    rap = fmaf(rv[j][c], ap[j], rap);
                    aa  = fmaf(ap[j], ap[j], aa);
                    rr  = fmaf(rv[j][c], rv[j][c], rr);
                }
                if (rowring) {
                    *(float4*)&apb[idxP + c * HW] = make_float4(ap[0], ap[1], ap[2], ap[3]);
                } else if (lx0 == 0) {
                    apb[idxP + c * HW]     = ap[0];
                    apb[idxP + c * HW + 1] = ap[1];
                } else if (lx0 == TX - 4) {
                    apb[idxP + c * HW + 2] = ap[2];
                    apb[idxP + c * HW + 3] = ap[3];
                }
            }
            block_reduce4(pd, rap, aa, rr, sRed);
            if (tid == 0)
                __stcg(&g_pd4[par][bid], make_float4(pd, rap, aa, rr));
        }
        gsync();   // the ONLY grid sync in the iteration

        // ---- fused B: scalars; x,r update; p = r + beta*p; refill sD ----
        {
            float sx, sy, sz, crit;
            reduce4_arr(par, sBc, sx, sy, sz, crit);     // identical everywhere
            if (!(crit >= TOLf)) break;     // reference 'active' gating: frozen
            float alphaf = crit / sx;
            float critn = fmaf(alphaf * alphaf, sz, fmaf(-2.f * alphaf, sy, crit));
            if (critn < 0.f) critn = 0.f;   // fp32 noise guard near convergence
            float betan = critn / crit;

            float dv[PPT] = {0.f, 0.f, 0.f, 0.f};
#pragma unroll
            for (int c = 0; c < 3; c++) {
                float4 mk4 = __ldg((const float4*)&mask[idxP + c * HW]);
                float mkj[4] = {mk4.x, mk4.y, mk4.z, mk4.w};
#pragma unroll
                for (int j = 0; j < PPT; j++) {
                    float apv  = fmaf(rho, pv[j][c], mkj[j] * mv[j]);
                    xv[j][c]   = fmaf(alphaf, pv[j][c], xv[j][c]);
                    float rnew = fmaf(-alphaf, apv, rv[j][c]);
                    float pnew = fmaf(betan, pv[j][c], rnew);
                    rv[j][c] = rnew;
                    pv[j][c] = pnew;
                    dv[j] = fmaf(mkj[j], pnew, dv[j]);
                }
            }
            *(float4*)&sD[(ly + 2) * SDW + lx0 + 4] =
                make_float4(dv[0], dv[1], dv[2], dv[3]);

            if (tid < NRING && hidx >= 0) {
                float dvh = 0.f;
#pragma unroll
                for (int c = 0; c < 3; c++) {
                    float hap = __ldcg(&apb[hidx + c * HW]);
                    float hrn = fmaf(-alphaf, hap, sHr[c][tid]);
                    float hpn = fmaf(betan, sHp[c][tid], hrn);
                    sHr[c][tid] = hrn;
                    sHp[c][tid] = hpn;
                    dvh = fmaf(sHm[c][tid], hpn, dvh);
                }
                sD[soff] = dvh;
            }
        }
        // no sync needed: next fill_t opens with __syncthreads; parity buffers
        // make the next Ap publish race-free vs this B's neighbor reads.
    }

    // ================= final: write x from registers (own points) ==========
#pragma unroll
    for (int c = 0; c < 3; c++)
        *(float4*)&xout[idxP + c * HW] =
            make_float4(xv[0][c], xv[1][c], xv[2][c], xv[3][c]);
}

extern "C" void kernel_launch(void* const* d_in, const int* in_sizes, int n_in,
                              void* d_out, int out_size) {
    (void)in_sizes; (void)n_in; (void)out_size;
    cg_kernel<<<NBLK, NTHR>>>(
        (const float*)d_in[0],   // mask  [4,3,256,256]
        (const float*)d_in[1],   // y     [4,256,256]
        (const float*)d_in[2],   // z     [4,3,256,256]
        (const float*)d_in[3],   // beta  [4,3,256,256]
        (const float*)d_in[4],   // rho   scalar
        (const float*)d_in[5],   // kernel[3,1,3,3]
        (float*)d_out);          // x     [4,3,256,256]
}